// round 14
// baseline (speedup 1.0000x reference)
#include <cuda_runtime.h>
#include <cuda_fp16.h>
#include <cstdint>

#define BATCH   4
#define TSEQ    2048
#define DM      1024
#define HEADS   16
#define DK      64
#define BT      (BATCH * TSEQ)   // 8192
#define LOG2E   1.4426950408889634f

// ---------------- scratch (device globals) ----------------------------------
__device__ unsigned short g_hq[BT * DM];     // fp16 Q input
__device__ unsigned short g_hkc[BT * DM];    // fp16 K input, mask-compacted rows
__device__ unsigned short g_hvc[BT * DM];    // fp16 V input, mask-compacted rows
__device__ unsigned short g_hw[4][DM * DM];  // fp16 weights
__device__ unsigned short g_qp[BT * DM];     // projected q (pre-scaled, log2 domain)
__device__ unsigned short g_kp[BT * DM];     // projected k (compacted)
__device__ unsigned short g_vp[BT * DM];     // projected v (compacted)
__device__ unsigned short g_ctx[BT * DM];    // attention output
__device__ int g_idx[BATCH * TSEQ];          // valid key indices per batch
__device__ int g_cnt[BATCH];                 // valid key counts

// ---------------- ptx helpers ------------------------------------------------
__device__ __forceinline__ uint32_t smem_u32(const void* p) {
    return (uint32_t)__cvta_generic_to_shared(p);
}
__device__ __forceinline__ void ldsm4(uint32_t r[4], uint32_t a) {
    asm volatile("ldmatrix.sync.aligned.m8n8.x4.shared.b16 {%0,%1,%2,%3}, [%4];"
                 : "=r"(r[0]), "=r"(r[1]), "=r"(r[2]), "=r"(r[3]) : "r"(a));
}
__device__ __forceinline__ void ldsm4t(uint32_t r[4], uint32_t a) {
    asm volatile("ldmatrix.sync.aligned.m8n8.x4.trans.shared.b16 {%0,%1,%2,%3}, [%4];"
                 : "=r"(r[0]), "=r"(r[1]), "=r"(r[2]), "=r"(r[3]) : "r"(a));
}
__device__ __forceinline__ void mma16816(float c[4],
    uint32_t a0, uint32_t a1, uint32_t a2, uint32_t a3, uint32_t b0, uint32_t b1) {
    asm volatile(
        "mma.sync.aligned.m16n8k16.row.col.f32.f16.f16.f32 "
        "{%0,%1,%2,%3}, {%4,%5,%6,%7}, {%8,%9}, {%0,%1,%2,%3};\n"
        : "+f"(c[0]), "+f"(c[1]), "+f"(c[2]), "+f"(c[3])
        : "r"(a0), "r"(a1), "r"(a2), "r"(a3), "r"(b0), "r"(b1));
}
__device__ __forceinline__ void cp16(uint32_t s, const void* g) {
    asm volatile("cp.async.cg.shared.global [%0], [%1], 16;" :: "r"(s), "l"(g));
}
__device__ __forceinline__ void cp_commit() {
    asm volatile("cp.async.commit_group;");
}
template<int N> __device__ __forceinline__ void cp_wait() {
    asm volatile("cp.async.wait_group %0;" :: "n"(N));
}
__device__ __forceinline__ uint32_t pkh2(float x, float y) {
    __half2 h = __floats2half2_rn(x, y);
    return *reinterpret_cast<uint32_t*>(&h);
}
__device__ __forceinline__ uint32_t h2exp2u(uint32_t a) {
    uint32_t d;
    asm("ex2.approx.f16x2 %0, %1;" : "=r"(d) : "r"(a));
    return d;
}

// ---------------- mask compaction (deterministic prefix scan) -----------------
__global__ void __launch_bounds__(256) compact_mask(
    const int* __restrict__ mask, int* __restrict__ idx, int* __restrict__ cnt)
{
    const int b = blockIdx.x;
    const int tid = threadIdx.x, lane = tid & 31, wid = tid >> 5;
    __shared__ int wtot[8];
    __shared__ int sbase;
    if (tid == 0) sbase = 0;
    __syncthreads();

    for (int c = 0; c < TSEQ; c += 256) {
        const int i = c + tid;
        const int v = mask[b * TSEQ + i] != 0;
        const unsigned bal = __ballot_sync(0xffffffffu, v);
        if (lane == 0) wtot[wid] = __popc(bal);
        __syncthreads();
        int off = sbase;
        for (int w = 0; w < wid; w++) off += wtot[w];
        off += __popc(bal & ((1u << lane) - 1));
        if (v) idx[b * TSEQ + off] = i;
        __syncthreads();
        if (tid == 0) {
            int t = 0;
            for (int w = 0; w < 8; w++) t += wtot[w];
            sbase += t;
        }
        __syncthreads();
    }
    if (tid == 0) cnt[b] = sbase;
}

// ---------------- merged prep: Q cvt + 4x W cvt + K/V gather-cvt --------------
__global__ void __launch_bounds__(256) prep(
    const float* __restrict__ Q,
    const float* __restrict__ w0, const float* __restrict__ w1,
    const float* __restrict__ w2, const float* __restrict__ w3,
    const float* __restrict__ K, const float* __restrict__ V,
    const int* __restrict__ idx, const int* __restrict__ cnt,
    unsigned short* __restrict__ hq, unsigned short* __restrict__ hw,
    unsigned short* __restrict__ kc, unsigned short* __restrict__ vc)
{
    const int bid = blockIdx.x, tid = threadIdx.x;

    if (bid < 4096) {
        const int i = (bid * 256 + tid) * 8;
        float4 v0 = *(const float4*)(Q + i);
        float4 v1 = *(const float4*)(Q + i + 4);
        uint4 u;
        u.x = pkh2(v0.x, v0.y); u.y = pkh2(v0.z, v0.w);
        u.z = pkh2(v1.x, v1.y); u.w = pkh2(v1.z, v1.w);
        *(uint4*)(hq + i) = u;
    } else if (bid < 6144) {
        const int wb = bid - 4096;
        const int z = wb >> 9;
        const float* s = (z == 0) ? w0 : (z == 1) ? w1 : (z == 2) ? w2 : w3;
        const int i = ((wb & 511) * 256 + tid) * 8;
        float4 v0 = *(const float4*)(s + i);
        float4 v1 = *(const float4*)(s + i + 4);
        uint4 u;
        u.x = pkh2(v0.x, v0.y); u.y = pkh2(v0.z, v0.w);
        u.z = pkh2(v1.x, v1.y); u.w = pkh2(v1.z, v1.w);
        *(uint4*)(hw + (size_t)z * (DM * DM) + i) = u;
    } else {
        const int row = (bid - 6144) * 2 + (tid >> 7);
        const int b = row >> 11, j = row & 2047;
        const int Nb = cnt[b];
        const int pad = (Nb + 127) & ~127;
        if (j >= pad) return;
        const int e = (tid & 127) * 8;
        const size_t dst = (size_t)row * DM + e;
        if (j < Nb) {
            const size_t src = ((size_t)(b * TSEQ) + idx[b * TSEQ + j]) * DM + e;
            float4 k0 = *(const float4*)(K + src);
            float4 k1 = *(const float4*)(K + src + 4);
            float4 v0 = *(const float4*)(V + src);
            float4 v1 = *(const float4*)(V + src + 4);
            uint4 ku, vu;
            ku.x = pkh2(k0.x, k0.y); ku.y = pkh2(k0.z, k0.w);
            ku.z = pkh2(k1.x, k1.y); ku.w = pkh2(k1.z, k1.w);
            vu.x = pkh2(v0.x, v0.y); vu.y = pkh2(v0.z, v0.w);
            vu.z = pkh2(v1.x, v1.y); vu.w = pkh2(v1.z, v1.w);
            *(uint4*)(kc + dst) = ku;
            *(uint4*)(vc + dst) = vu;
        } else {
            *(uint4*)(kc + dst) = make_uint4(0, 0, 0, 0);
            *(uint4*)(vc + dst) = make_uint4(0, 0, 0, 0);
        }
    }
}

// ---------------- GEMM body (R13 proven): 128x128, warp 64x32, 1 barrier ------
template<bool OUT_HALF>
__device__ __forceinline__ void gemm_body(
    const __half* __restrict__ A, const __half* __restrict__ W,
    const float* __restrict__ bias, void* __restrict__ Cv, float scale,
    int bm, int bn)
{
    __shared__ __half As[2][128][40];
    __shared__ __half Ws[2][128][40];

    const int tid = threadIdx.x, lane = tid & 31, wid = tid >> 5;
    const int g = lane >> 2, t = lane & 3;
    const int wm = (wid >> 2) * 64, wn = (wid & 3) * 32;

    const int r0 = tid >> 2;
    const int r1 = 64 + r0;
    const int o0 = (tid & 3) * 8;

    const __half* Ag = A + (size_t)bm * DM;
    const __half* Wg = W + (size_t)bn * DM;

    float acc[4][4][4] = {};

    auto stage = [&](int buf, int k0) {
        cp16(smem_u32(&As[buf][r0][o0]), Ag + (size_t)r0 * DM + k0 + o0);
        cp16(smem_u32(&As[buf][r1][o0]), Ag + (size_t)r1 * DM + k0 + o0);
        cp16(smem_u32(&Ws[buf][r0][o0]), Wg + (size_t)r0 * DM + k0 + o0);
        cp16(smem_u32(&Ws[buf][r1][o0]), Wg + (size_t)r1 * DM + k0 + o0);
    };

    stage(0, 0); cp_commit();

    const int lrow = lane & 15, lcol = (lane >> 4) * 8;

    for (int kt = 0; kt < 32; kt++) {
        const int cur = kt & 1;
        cp_wait<0>();
        __syncthreads();
        if (kt < 31) { stage(cur ^ 1, (kt + 1) * 32); cp_commit(); }

#pragma unroll
        for (int kk = 0; kk < 2; kk++) {
            uint32_t a[4][4], bf[2][4];
#pragma unroll
            for (int mt = 0; mt < 4; mt++)
                ldsm4(a[mt], smem_u32(&As[cur][wm + mt * 16 + lrow][kk * 16 + lcol]));
#pragma unroll
            for (int ng = 0; ng < 2; ng++)
                ldsm4(bf[ng], smem_u32(&Ws[cur][wn + ng * 16 + lrow][kk * 16 + lcol]));
#pragma unroll
            for (int mt = 0; mt < 4; mt++)
#pragma unroll
                for (int nt = 0; nt < 4; nt++) {
                    const uint32_t b0 = (nt & 1) ? bf[nt >> 1][1] : bf[nt >> 1][0];
                    const uint32_t b1 = (nt & 1) ? bf[nt >> 1][3] : bf[nt >> 1][2];
                    mma16816(acc[mt][nt], a[mt][0], a[mt][1], a[mt][2], a[mt][3], b0, b1);
                }
        }
    }

#pragma unroll
    for (int nt = 0; nt < 4; nt++) {
        const int col = bn + wn + nt * 8 + 2 * t;
        const float bb0 = bias[col], bb1 = bias[col + 1];
#pragma unroll
        for (int mt = 0; mt < 4; mt++) {
            const int row = bm + wm + mt * 16 + g;
            const float x0 = (acc[mt][nt][0] + bb0) * scale;
            const float x1 = (acc[mt][nt][1] + bb1) * scale;
            const float x2 = (acc[mt][nt][2] + bb0) * scale;
            const float x3 = (acc[mt][nt][3] + bb1) * scale;
            if (OUT_HALF) {
                __half* C = (__half*)Cv;
                *(__half2*)(C + (size_t)row * DM + col)       = __floats2half2_rn(x0, x1);
                *(__half2*)(C + (size_t)(row + 8) * DM + col) = __floats2half2_rn(x2, x3);
            } else {
                float* C = (float*)Cv;
                *(float2*)(C + (size_t)row * DM + col)       = make_float2(x0, x1);
                *(float2*)(C + (size_t)(row + 8) * DM + col) = make_float2(x2, x3);
            }
        }
    }
}

__global__ void __launch_bounds__(256) gemm_qkv(
    const __half* __restrict__ Aq, const __half* __restrict__ Ak,
    const __half* __restrict__ Av, const __half* __restrict__ Wall,
    const float* __restrict__ bq, const float* __restrict__ bk,
    const float* __restrict__ bv,
    __half* __restrict__ Cq, __half* __restrict__ Ck, __half* __restrict__ Cv2,
    const int* __restrict__ cnt)
{
    const int z = blockIdx.z;
    const int bm = blockIdx.y * 128, bn = blockIdx.x * 128;
    if (z != 0) {
        const int Nb = cnt[bm >> 11];
        if ((bm & 2047) >= ((Nb + 127) & ~127)) return;
    }
    const __half* A = (z == 0) ? Aq : (z == 1) ? Ak : Av;
    const __half* W = Wall + (size_t)z * (DM * DM);
    const float* bias = (z == 0) ? bq : (z == 1) ? bk : bv;
    __half* C = (z == 0) ? Cq : (z == 1) ? Ck : Cv2;
    const float scale = (z == 0) ? (0.125f * LOG2E) : 1.0f;
    gemm_body<true>(A, W, bias, C, scale, bm, bn);
}

__global__ void __launch_bounds__(256) gemm_out(
    const __half* __restrict__ A, const __half* __restrict__ W,
    const float* __restrict__ bias, float* __restrict__ C)
{
    gemm_body<false>(A, W, bias, C, 1.0f, blockIdx.y * 128, blockIdx.x * 128);
}

// ---------------- fp16 flash attention over compacted keys --------------------
// Block = one (b,h) x 128 q-rows, 128 threads = 4 warps, each warp owns 32
// q-rows (2 m16 tiles) which SHARE every K/V fragment: 4 mma per ldsm instead
// of 2 -> smem fragment traffic per q-row halves (L1 was the 58% ceiling).
// Same per-row accumulation order as before (bit-identical).
__global__ void __launch_bounds__(128) attn_h(
    const __half* __restrict__ qp, const __half* __restrict__ kp,
    const __half* __restrict__ vp, const int* __restrict__ cnt,
    __half* __restrict__ ctx)
{
    __shared__ __half Ks[2][64][72];
    __shared__ __half Vs[2][64][72];

    const int tid = threadIdx.x, lane = tid & 31, wq = tid >> 5;  // wq: 0..3
    const int g = lane >> 2, t = lane & 3;
    const int bh = blockIdx.y, b = bh >> 4, h = bh & 15;
    const int q0 = blockIdx.x * 128;
    const int Nb = cnt[b];
    const int NT = (Nb + 63) >> 6;
    const bool partial = (Nb & 63) != 0;

    const uint32_t bones = (g == 0) ? 0x3C003C00u : 0u;

    const __half* kg = kp + (size_t)b * TSEQ * DM + h * DK;
    const __half* vg = vp + (size_t)b * TSEQ * DM + h * DK;

    // Q fragments: 2 m16 tiles per warp
    uint32_t qf[2][4][4];
#pragma unroll
    for (int mt = 0; mt < 2; mt++) {
        const __half* qb  = qp + (size_t)(b * TSEQ + q0 + wq * 32 + mt * 16) * DM + h * DK;
        const __half* qr0 = qb + (size_t)g * DM + 2 * t;
        const __half* qr1 = qb + (size_t)(g + 8) * DM + 2 * t;
#pragma unroll
        for (int ks = 0; ks < 4; ks++) {
            qf[mt][ks][0] = *(const uint32_t*)(qr0 + ks * 16);
            qf[mt][ks][1] = *(const uint32_t*)(qr1 + ks * 16);
            qf[mt][ks][2] = *(const uint32_t*)(qr0 + ks * 16 + 8);
            qf[mt][ks][3] = *(const uint32_t*)(qr1 + ks * 16 + 8);
        }
    }

    // staging: 128 threads, 2 threads/row, 4 cp16 per array each
    const int sr = tid >> 1;
    const int so = (tid & 1) * 32;

    auto stage = [&](int buf, int j0) {
        const __half* kr = kg + (size_t)(j0 + sr) * DM + so;
        const __half* vr = vg + (size_t)(j0 + sr) * DM + so;
#pragma unroll
        for (int i = 0; i < 4; i++) {
            cp16(smem_u32(&Ks[buf][sr][so + i * 8]), kr + i * 8);
            cp16(smem_u32(&Vs[buf][sr][so + i * 8]), vr + i * 8);
        }
    };

    float of[2][8][4] = {};
    float lfrag[2][4] = {};
    float m[2][2];
    m[0][0] = m[0][1] = m[1][0] = m[1][1] = -1e30f;

    stage(0, 0); cp_commit();

    const int lrow = lane & 15, lcol = (lane >> 4) * 8;

    for (int jt = 0; jt < NT; jt++) {
        const int cur = jt & 1;
        cp_wait<0>();
        __syncthreads();
        if (jt < NT - 1) { stage(cur ^ 1, (jt + 1) * 64); cp_commit(); }

        // ---- S = Q @ K^T : kb fragments shared across both m-tiles ----
        float sf[2][8][4] = {};
#pragma unroll
        for (int ks = 0; ks < 4; ks++)
#pragma unroll
            for (int ng = 0; ng < 4; ng++) {
                uint32_t kb[4];
                ldsm4(kb, smem_u32(&Ks[cur][ng * 16 + lrow][ks * 16 + lcol]));
#pragma unroll
                for (int mt = 0; mt < 2; mt++) {
                    mma16816(sf[mt][2 * ng],     qf[mt][ks][0], qf[mt][ks][1],
                             qf[mt][ks][2], qf[mt][ks][3], kb[0], kb[2]);
                    mma16816(sf[mt][2 * ng + 1], qf[mt][ks][0], qf[mt][ks][1],
                             qf[mt][ks][2], qf[mt][ks][3], kb[1], kb[3]);
                }
            }

        // ---- mask only on the final partial tile (column-dependent only) ----
        if (partial && jt == NT - 1) {
            const int jb = jt * 64 + 2 * t;
#pragma unroll
            for (int nt = 0; nt < 8; nt++) {
                const float a0 = (jb + nt * 8)     < Nb ? 0.f : -1e30f;
                const float a1 = (jb + nt * 8 + 1) < Nb ? 0.f : -1e30f;
#pragma unroll
                for (int mt = 0; mt < 2; mt++) {
                    sf[mt][nt][0] += a0; sf[mt][nt][1] += a1;
                    sf[mt][nt][2] += a0; sf[mt][nt][3] += a1;
                }
            }
        }

        // ---- online max (per m-tile, per row-half) ----
        float mn[2][2];
#pragma unroll
        for (int mt = 0; mt < 2; mt++) {
            float mn0 = m[mt][0], mn1 = m[mt][1];
#pragma unroll
            for (int nt = 0; nt < 8; nt++) {
                mn0 = fmaxf(mn0, fmaxf(sf[mt][nt][0], sf[mt][nt][1]));
                mn1 = fmaxf(mn1, fmaxf(sf[mt][nt][2], sf[mt][nt][3]));
            }
            mn0 = fmaxf(mn0, __shfl_xor_sync(0xffffffffu, mn0, 1));
            mn0 = fmaxf(mn0, __shfl_xor_sync(0xffffffffu, mn0, 2));
            mn1 = fmaxf(mn1, __shfl_xor_sync(0xffffffffu, mn1, 1));
            mn1 = fmaxf(mn1, __shfl_xor_sync(0xffffffffu, mn1, 2));
            mn[mt][0] = mn0; mn[mt][1] = mn1;
        }

        // ---- skip-rescale when no row's max advanced (exact) ----
        const bool changed = __any_sync(0xffffffffu,
            (mn[0][0] > m[0][0]) || (mn[0][1] > m[0][1]) ||
            (mn[1][0] > m[1][0]) || (mn[1][1] > m[1][1]));
        if (changed) {
#pragma unroll
            for (int mt = 0; mt < 2; mt++) {
                const float c0 = exp2f(m[mt][0] - mn[mt][0]);
                const float c1 = exp2f(m[mt][1] - mn[mt][1]);
#pragma unroll
                for (int nt = 0; nt < 8; nt++) {
                    of[mt][nt][0] *= c0; of[mt][nt][1] *= c0;
                    of[mt][nt][2] *= c1; of[mt][nt][3] *= c1;
                }
                lfrag[mt][0] *= c0; lfrag[mt][2] *= c1;
            }
        }
#pragma unroll
        for (int mt = 0; mt < 2; mt++) { m[mt][0] = mn[mt][0]; m[mt][1] = mn[mt][1]; }

        // ---- P = exp2(S - m) in fp16x2 ----
        uint32_t ph[2][8][2];
#pragma unroll
        for (int mt = 0; mt < 2; mt++)
#pragma unroll
            for (int nt = 0; nt < 8; nt++) {
                ph[mt][nt][0] = h2exp2u(pkh2(sf[mt][nt][0] - m[mt][0],
                                             sf[mt][nt][1] - m[mt][0]));
                ph[mt][nt][1] = h2exp2u(pkh2(sf[mt][nt][2] - m[mt][1],
                                             sf[mt][nt][3] - m[mt][1]));
            }

        // ---- O += P @ V ; l += P @ ones : vb shared across both m-tiles ----
#pragma unroll
        for (int kq = 0; kq < 4; kq++) {
#pragma unroll
            for (int mt = 0; mt < 2; mt++)
                mma16816(lfrag[mt], ph[mt][2 * kq][0], ph[mt][2 * kq][1],
                         ph[mt][2 * kq + 1][0], ph[mt][2 * kq + 1][1], bones, bones);
#pragma unroll
            for (int dg = 0; dg < 4; dg++) {
                uint32_t vb[4];
                ldsm4t(vb, smem_u32(&Vs[cur][kq * 16 + lrow][dg * 16 + lcol]));
#pragma unroll
                for (int mt = 0; mt < 2; mt++) {
                    mma16816(of[mt][2 * dg],     ph[mt][2 * kq][0], ph[mt][2 * kq][1],
                             ph[mt][2 * kq + 1][0], ph[mt][2 * kq + 1][1], vb[0], vb[1]);
                    mma16816(of[mt][2 * dg + 1], ph[mt][2 * kq][0], ph[mt][2 * kq][1],
                             ph[mt][2 * kq + 1][0], ph[mt][2 * kq + 1][1], vb[2], vb[3]);
                }
            }
        }
    }

    // ---- epilogue ----
#pragma unroll
    for (int mt = 0; mt < 2; mt++) {
        const float l0 = __shfl_sync(0xffffffffu, lfrag[mt][0], lane & 28);
        const float l1 = __shfl_sync(0xffffffffu, lfrag[mt][2], lane & 28);
        const float i0 = 1.f / l0, i1 = 1.f / l1;
        __half* d0 = ctx + (size_t)(b * TSEQ + q0 + wq * 32 + mt * 16 + g) * DM + h * DK;
        __half* d1 = d0 + (size_t)8 * DM;
#pragma unroll
        for (int nt = 0; nt < 8; nt++) {
            const int col = nt * 8 + 2 * t;
            *(__half2*)(d0 + col) = __floats2half2_rn(of[mt][nt][0] * i0, of[mt][nt][1] * i0);
            *(__half2*)(d1 + col) = __floats2half2_rn(of[mt][nt][2] * i1, of[mt][nt][3] * i1);
        }
    }
}

// ---------------- launch --------------------------------------------------------
extern "C" void kernel_launch(void* const* d_in, const int* in_sizes, int n_in,
                              void* d_out, int out_size)
{
    const float* Q    = (const float*)d_in[0];
    const float* Kin  = (const float*)d_in[1];
    const float* Vin  = (const float*)d_in[2];
    const int*   mask = (const int*)  d_in[3];
    const float* W_q  = (const float*)d_in[4];
    const float* b_q  = (const float*)d_in[5];
    const float* W_k  = (const float*)d_in[6];
    const float* b_k  = (const float*)d_in[7];
    const float* W_v  = (const float*)d_in[8];
    const float* b_v  = (const float*)d_in[9];
    const float* W_o  = (const float*)d_in[10];
    const float* b_o  = (const float*)d_in[11];
    float* out = (float*)d_out;

    unsigned short *hq, *hkc, *hvc, *hw, *qp, *kp, *vp, *ctx;
    int *idx, *cnt;
    cudaGetSymbolAddress((void**)&hq,  g_hq);
    cudaGetSymbolAddress((void**)&hkc, g_hkc);
    cudaGetSymbolAddress((void**)&hvc, g_hvc);
    cudaGetSymbolAddress((void**)&hw,  g_hw);
    cudaGetSymbolAddress((void**)&qp,  g_qp);
    cudaGetSymbolAddress((void**)&kp,  g_kp);
    cudaGetSymbolAddress((void**)&vp,  g_vp);
    cudaGetSymbolAddress((void**)&ctx, g_ctx);
    cudaGetSymbolAddress((void**)&idx, g_idx);
    cudaGetSymbolAddress((void**)&cnt, g_cnt);

    const int nW = DM * DM;       // 1048576

    compact_mask<<<BATCH, 256>>>(mask, idx, cnt);

    prep<<<10240, 256>>>(Q, W_q, W_k, W_v, W_o, Kin, Vin, idx, cnt,
                         hq, hw, hkc, hvc);

    gemm_qkv<<<dim3(DM / 128, BT / 128, 3), 256>>>(
        (const __half*)hq, (const __half*)hkc, (const __half*)hvc,
        (const __half*)hw, b_q, b_k, b_v,
        (__half*)qp, (__half*)kp, (__half*)vp, cnt);

    attn_h<<<dim3(TSEQ / 128, BATCH * HEADS), 128>>>(
        (const __half*)qp, (const __half*)kp, (const __half*)vp, cnt, (__half*)ctx);

    gemm_out<<<dim3(DM / 128, BT / 128), 256>>>(
        (const __half*)ctx, (const __half*)(hw + 3 * (size_t)nW), b_o, out);
}

// round 15
// speedup vs baseline: 1.0213x; 1.0213x over previous
#include <cuda_runtime.h>
#include <cuda_fp16.h>
#include <cstdint>

#define BATCH   4
#define TSEQ    2048
#define DM      1024
#define HEADS   16
#define DK      64
#define BT      (BATCH * TSEQ)   // 8192
#define LOG2E   1.4426950408889634f

// 3-stage GEMM smem: As[3][128][40] + Ws[3][128][40] halves = 61440 bytes
#define GEMM_SMEM_BYTES (6 * 128 * 40 * 2)

// ---------------- scratch (device globals) ----------------------------------
__device__ unsigned short g_hq[BT * DM];     // fp16 Q input
__device__ unsigned short g_hkc[BT * DM];    // fp16 K input, mask-compacted rows
__device__ unsigned short g_hvc[BT * DM];    // fp16 V input, mask-compacted rows
__device__ unsigned short g_hw[4][DM * DM];  // fp16 weights
__device__ unsigned short g_qp[BT * DM];     // projected q (pre-scaled, log2 domain)
__device__ unsigned short g_kp[BT * DM];     // projected k (compacted)
__device__ unsigned short g_vp[BT * DM];     // projected v (compacted)
__device__ unsigned short g_ctx[BT * DM];    // attention output
__device__ int g_idx[BATCH * TSEQ];          // valid key indices per batch
__device__ int g_cnt[BATCH];                 // valid key counts

// ---------------- ptx helpers ------------------------------------------------
__device__ __forceinline__ uint32_t smem_u32(const void* p) {
    return (uint32_t)__cvta_generic_to_shared(p);
}
__device__ __forceinline__ void ldsm4(uint32_t r[4], uint32_t a) {
    asm volatile("ldmatrix.sync.aligned.m8n8.x4.shared.b16 {%0,%1,%2,%3}, [%4];"
                 : "=r"(r[0]), "=r"(r[1]), "=r"(r[2]), "=r"(r[3]) : "r"(a));
}
__device__ __forceinline__ void ldsm4t(uint32_t r[4], uint32_t a) {
    asm volatile("ldmatrix.sync.aligned.m8n8.x4.trans.shared.b16 {%0,%1,%2,%3}, [%4];"
                 : "=r"(r[0]), "=r"(r[1]), "=r"(r[2]), "=r"(r[3]) : "r"(a));
}
__device__ __forceinline__ void mma16816(float c[4],
    uint32_t a0, uint32_t a1, uint32_t a2, uint32_t a3, uint32_t b0, uint32_t b1) {
    asm volatile(
        "mma.sync.aligned.m16n8k16.row.col.f32.f16.f16.f32 "
        "{%0,%1,%2,%3}, {%4,%5,%6,%7}, {%8,%9}, {%0,%1,%2,%3};\n"
        : "+f"(c[0]), "+f"(c[1]), "+f"(c[2]), "+f"(c[3])
        : "r"(a0), "r"(a1), "r"(a2), "r"(a3), "r"(b0), "r"(b1));
}
__device__ __forceinline__ void cp16(uint32_t s, const void* g) {
    asm volatile("cp.async.cg.shared.global [%0], [%1], 16;" :: "r"(s), "l"(g));
}
__device__ __forceinline__ void cp_commit() {
    asm volatile("cp.async.commit_group;");
}
template<int N> __device__ __forceinline__ void cp_wait() {
    asm volatile("cp.async.wait_group %0;" :: "n"(N));
}
__device__ __forceinline__ uint32_t pkh2(float x, float y) {
    __half2 h = __floats2half2_rn(x, y);
    return *reinterpret_cast<uint32_t*>(&h);
}
__device__ __forceinline__ uint32_t h2exp2u(uint32_t a) {
    uint32_t d;
    asm("ex2.approx.f16x2 %0, %1;" : "=r"(d) : "r"(a));
    return d;
}

// ---------------- mask compaction (deterministic prefix scan) -----------------
__global__ void __launch_bounds__(256) compact_mask(
    const int* __restrict__ mask, int* __restrict__ idx, int* __restrict__ cnt)
{
    const int b = blockIdx.x;
    const int tid = threadIdx.x, lane = tid & 31, wid = tid >> 5;
    __shared__ int wtot[8];
    __shared__ int sbase;
    if (tid == 0) sbase = 0;
    __syncthreads();

    for (int c = 0; c < TSEQ; c += 256) {
        const int i = c + tid;
        const int v = mask[b * TSEQ + i] != 0;
        const unsigned bal = __ballot_sync(0xffffffffu, v);
        if (lane == 0) wtot[wid] = __popc(bal);
        __syncthreads();
        int off = sbase;
        for (int w = 0; w < wid; w++) off += wtot[w];
        off += __popc(bal & ((1u << lane) - 1));
        if (v) idx[b * TSEQ + off] = i;
        __syncthreads();
        if (tid == 0) {
            int t = 0;
            for (int w = 0; w < 8; w++) t += wtot[w];
            sbase += t;
        }
        __syncthreads();
    }
    if (tid == 0) cnt[b] = sbase;
}

// ---------------- merged prep: Q cvt + 4x W cvt + K/V gather-cvt --------------
__global__ void __launch_bounds__(256) prep(
    const float* __restrict__ Q,
    const float* __restrict__ w0, const float* __restrict__ w1,
    const float* __restrict__ w2, const float* __restrict__ w3,
    const float* __restrict__ K, const float* __restrict__ V,
    const int* __restrict__ idx, const int* __restrict__ cnt,
    unsigned short* __restrict__ hq, unsigned short* __restrict__ hw,
    unsigned short* __restrict__ kc, unsigned short* __restrict__ vc)
{
    const int bid = blockIdx.x, tid = threadIdx.x;

    if (bid < 4096) {
        const int i = (bid * 256 + tid) * 8;
        float4 v0 = *(const float4*)(Q + i);
        float4 v1 = *(const float4*)(Q + i + 4);
        uint4 u;
        u.x = pkh2(v0.x, v0.y); u.y = pkh2(v0.z, v0.w);
        u.z = pkh2(v1.x, v1.y); u.w = pkh2(v1.z, v1.w);
        *(uint4*)(hq + i) = u;
    } else if (bid < 6144) {
        const int wb = bid - 4096;
        const int z = wb >> 9;
        const float* s = (z == 0) ? w0 : (z == 1) ? w1 : (z == 2) ? w2 : w3;
        const int i = ((wb & 511) * 256 + tid) * 8;
        float4 v0 = *(const float4*)(s + i);
        float4 v1 = *(const float4*)(s + i + 4);
        uint4 u;
        u.x = pkh2(v0.x, v0.y); u.y = pkh2(v0.z, v0.w);
        u.z = pkh2(v1.x, v1.y); u.w = pkh2(v1.z, v1.w);
        *(uint4*)(hw + (size_t)z * (DM * DM) + i) = u;
    } else {
        const int row = (bid - 6144) * 2 + (tid >> 7);
        const int b = row >> 11, j = row & 2047;
        const int Nb = cnt[b];
        const int pad = (Nb + 127) & ~127;
        if (j >= pad) return;
        const int e = (tid & 127) * 8;
        const size_t dst = (size_t)row * DM + e;
        if (j < Nb) {
            const size_t src = ((size_t)(b * TSEQ) + idx[b * TSEQ + j]) * DM + e;
            float4 k0 = *(const float4*)(K + src);
            float4 k1 = *(const float4*)(K + src + 4);
            float4 v0 = *(const float4*)(V + src);
            float4 v1 = *(const float4*)(V + src + 4);
            uint4 ku, vu;
            ku.x = pkh2(k0.x, k0.y); ku.y = pkh2(k0.z, k0.w);
            ku.z = pkh2(k1.x, k1.y); ku.w = pkh2(k1.z, k1.w);
            vu.x = pkh2(v0.x, v0.y); vu.y = pkh2(v0.z, v0.w);
            vu.z = pkh2(v1.x, v1.y); vu.w = pkh2(v1.z, v1.w);
            *(uint4*)(kc + dst) = ku;
            *(uint4*)(vc + dst) = vu;
        } else {
            *(uint4*)(kc + dst) = make_uint4(0, 0, 0, 0);
            *(uint4*)(vc + dst) = make_uint4(0, 0, 0, 0);
        }
    }
}

// ---------------- GEMM body: 128x128 tile, warp 64x32, 3-stage pipeline -------
// Identical tiles/staging to R13; third buffer + cp_wait<1> gives the prefetch
// two compute bodies of slack (GEMM was latency-bound: nothing saturated).
template<bool OUT_HALF>
__device__ __forceinline__ void gemm_body(
    const __half* __restrict__ A, const __half* __restrict__ W,
    const float* __restrict__ bias, void* __restrict__ Cv, float scale,
    int bm, int bn)
{
    extern __shared__ __half sm[];
    __half* Asb = sm;                  // [3][128][40]
    __half* Wsb = sm + 3 * 128 * 40;   // [3][128][40]

    const int tid = threadIdx.x, lane = tid & 31, wid = tid >> 5;
    const int g = lane >> 2, t = lane & 3;
    const int wm = (wid >> 2) * 64, wn = (wid & 3) * 32;

    const int r0 = tid >> 2;
    const int r1 = 64 + r0;
    const int o0 = (tid & 3) * 8;

    const __half* Ag = A + (size_t)bm * DM;
    const __half* Wg = W + (size_t)bn * DM;

    float acc[4][4][4] = {};

    auto stage = [&](int buf, int k0) {
        __half* Ab = Asb + buf * (128 * 40);
        __half* Wb = Wsb + buf * (128 * 40);
        cp16(smem_u32(Ab + r0 * 40 + o0), Ag + (size_t)r0 * DM + k0 + o0);
        cp16(smem_u32(Ab + r1 * 40 + o0), Ag + (size_t)r1 * DM + k0 + o0);
        cp16(smem_u32(Wb + r0 * 40 + o0), Wg + (size_t)r0 * DM + k0 + o0);
        cp16(smem_u32(Wb + r1 * 40 + o0), Wg + (size_t)r1 * DM + k0 + o0);
    };

    stage(0, 0);  cp_commit();
    stage(1, 32); cp_commit();

    const int lrow = lane & 15, lcol = (lane >> 4) * 8;

    int cur = 0;
    for (int kt = 0; kt < 32; kt++) {
        if (kt < 30) cp_wait<1>();   // oldest group (this tile) landed
        else         cp_wait<0>();   // tail: drain everything
        __syncthreads();             // all warps done reading the buffer we stage next
        if (kt < 30) {
            int nb = cur + 2; if (nb >= 3) nb -= 3;
            stage(nb, (kt + 2) * 32); cp_commit();
        }

        const __half* Ab = Asb + cur * (128 * 40);
        const __half* Wb = Wsb + cur * (128 * 40);

#pragma unroll
        for (int kk = 0; kk < 2; kk++) {
            uint32_t a[4][4], bf[2][4];
#pragma unroll
            for (int mt = 0; mt < 4; mt++)
                ldsm4(a[mt], smem_u32(Ab + (wm + mt * 16 + lrow) * 40 + kk * 16 + lcol));
#pragma unroll
            for (int ng = 0; ng < 2; ng++)
                ldsm4(bf[ng], smem_u32(Wb + (wn + ng * 16 + lrow) * 40 + kk * 16 + lcol));
#pragma unroll
            for (int mt = 0; mt < 4; mt++)
#pragma unroll
                for (int nt = 0; nt < 4; nt++) {
                    const uint32_t b0 = (nt & 1) ? bf[nt >> 1][1] : bf[nt >> 1][0];
                    const uint32_t b1 = (nt & 1) ? bf[nt >> 1][3] : bf[nt >> 1][2];
                    mma16816(acc[mt][nt], a[mt][0], a[mt][1], a[mt][2], a[mt][3], b0, b1);
                }
        }
        if (++cur == 3) cur = 0;
    }

#pragma unroll
    for (int nt = 0; nt < 4; nt++) {
        const int col = bn + wn + nt * 8 + 2 * t;
        const float bb0 = bias[col], bb1 = bias[col + 1];
#pragma unroll
        for (int mt = 0; mt < 4; mt++) {
            const int row = bm + wm + mt * 16 + g;
            const float x0 = (acc[mt][nt][0] + bb0) * scale;
            const float x1 = (acc[mt][nt][1] + bb1) * scale;
            const float x2 = (acc[mt][nt][2] + bb0) * scale;
            const float x3 = (acc[mt][nt][3] + bb1) * scale;
            if (OUT_HALF) {
                __half* C = (__half*)Cv;
                *(__half2*)(C + (size_t)row * DM + col)       = __floats2half2_rn(x0, x1);
                *(__half2*)(C + (size_t)(row + 8) * DM + col) = __floats2half2_rn(x2, x3);
            } else {
                float* C = (float*)Cv;
                *(float2*)(C + (size_t)row * DM + col)       = make_float2(x0, x1);
                *(float2*)(C + (size_t)(row + 8) * DM + col) = make_float2(x2, x3);
            }
        }
    }
}

__global__ void __launch_bounds__(256) gemm_qkv(
    const __half* __restrict__ Aq, const __half* __restrict__ Ak,
    const __half* __restrict__ Av, const __half* __restrict__ Wall,
    const float* __restrict__ bq, const float* __restrict__ bk,
    const float* __restrict__ bv,
    __half* __restrict__ Cq, __half* __restrict__ Ck, __half* __restrict__ Cv2,
    const int* __restrict__ cnt)
{
    const int z = blockIdx.z;
    const int bm = blockIdx.y * 128, bn = blockIdx.x * 128;
    if (z != 0) {
        const int Nb = cnt[bm >> 11];
        if ((bm & 2047) >= ((Nb + 127) & ~127)) return;
    }
    const __half* A = (z == 0) ? Aq : (z == 1) ? Ak : Av;
    const __half* W = Wall + (size_t)z * (DM * DM);
    const float* bias = (z == 0) ? bq : (z == 1) ? bk : bv;
    __half* C = (z == 0) ? Cq : (z == 1) ? Ck : Cv2;
    const float scale = (z == 0) ? (0.125f * LOG2E) : 1.0f;
    gemm_body<true>(A, W, bias, C, scale, bm, bn);
}

__global__ void __launch_bounds__(256) gemm_out(
    const __half* __restrict__ A, const __half* __restrict__ W,
    const float* __restrict__ bias, float* __restrict__ C)
{
    gemm_body<false>(A, W, bias, C, 1.0f, blockIdx.y * 128, blockIdx.x * 128);
}

// ---------------- fp16 flash attention (R13 proven config) --------------------
// Block = one (b,h) x 128 q-rows, 256 threads. fp16x2 exponentials; l via
// ones-column mma; mask on final partial tile only; skip-rescale when max
// unchanged (exact); single __syncthreads per key tile.
__global__ void __launch_bounds__(256) attn_h(
    const __half* __restrict__ qp, const __half* __restrict__ kp,
    const __half* __restrict__ vp, const int* __restrict__ cnt,
    __half* __restrict__ ctx)
{
    __shared__ __half Ks[2][64][72];
    __shared__ __half Vs[2][64][72];

    const int tid = threadIdx.x, lane = tid & 31, wq = tid >> 5;
    const int g = lane >> 2, t = lane & 3;
    const int bh = blockIdx.y, b = bh >> 4, h = bh & 15;
    const int q0 = blockIdx.x * 128;
    const int Nb = cnt[b];
    const int NT = (Nb + 63) >> 6;
    const bool partial = (Nb & 63) != 0;

    const uint32_t bones = (g == 0) ? 0x3C003C00u : 0u;

    const __half* kg = kp + (size_t)b * TSEQ * DM + h * DK;
    const __half* vg = vp + (size_t)b * TSEQ * DM + h * DK;

    uint32_t qf[4][4];
    {
        const __half* qb  = qp + (size_t)(b * TSEQ + q0 + wq * 16) * DM + h * DK;
        const __half* qr0 = qb + (size_t)g * DM + 2 * t;
        const __half* qr1 = qb + (size_t)(g + 8) * DM + 2 * t;
#pragma unroll
        for (int ks = 0; ks < 4; ks++) {
            qf[ks][0] = *(const uint32_t*)(qr0 + ks * 16);
            qf[ks][1] = *(const uint32_t*)(qr1 + ks * 16);
            qf[ks][2] = *(const uint32_t*)(qr0 + ks * 16 + 8);
            qf[ks][3] = *(const uint32_t*)(qr1 + ks * 16 + 8);
        }
    }

    const int sr0 = tid >> 3;
    const int sr1 = 32 + sr0;
    const int so  = (tid & 7) * 8;

    auto stage = [&](int buf, int j0) {
        cp16(smem_u32(&Ks[buf][sr0][so]), kg + (size_t)(j0 + sr0) * DM + so);
        cp16(smem_u32(&Ks[buf][sr1][so]), kg + (size_t)(j0 + sr1) * DM + so);
        cp16(smem_u32(&Vs[buf][sr0][so]), vg + (size_t)(j0 + sr0) * DM + so);
        cp16(smem_u32(&Vs[buf][sr1][so]), vg + (size_t)(j0 + sr1) * DM + so);
    };

    float of[8][4] = {};
    float lfrag[4] = {};
    float m0 = -1e30f, m1 = -1e30f;

    stage(0, 0); cp_commit();

    const int lrow = lane & 15, lcol = (lane >> 4) * 8;

    for (int jt = 0; jt < NT; jt++) {
        const int cur = jt & 1;
        cp_wait<0>();
        __syncthreads();
        if (jt < NT - 1) { stage(cur ^ 1, (jt + 1) * 64); cp_commit(); }

        float sf[8][4] = {};
#pragma unroll
        for (int ks = 0; ks < 4; ks++)
#pragma unroll
            for (int ng = 0; ng < 4; ng++) {
                uint32_t kb[4];
                ldsm4(kb, smem_u32(&Ks[cur][ng * 16 + lrow][ks * 16 + lcol]));
                mma16816(sf[2 * ng],     qf[ks][0], qf[ks][1], qf[ks][2], qf[ks][3], kb[0], kb[2]);
                mma16816(sf[2 * ng + 1], qf[ks][0], qf[ks][1], qf[ks][2], qf[ks][3], kb[1], kb[3]);
            }

        if (partial && jt == NT - 1) {
            const int jb = jt * 64 + 2 * t;
#pragma unroll
            for (int nt = 0; nt < 8; nt++) {
                const float a0 = (jb + nt * 8)     < Nb ? 0.f : -1e30f;
                const float a1 = (jb + nt * 8 + 1) < Nb ? 0.f : -1e30f;
                sf[nt][0] += a0; sf[nt][1] += a1;
                sf[nt][2] += a0; sf[nt][3] += a1;
            }
        }

        float mn0 = m0, mn1 = m1;
#pragma unroll
        for (int nt = 0; nt < 8; nt++) {
            mn0 = fmaxf(mn0, fmaxf(sf[nt][0], sf[nt][1]));
            mn1 = fmaxf(mn1, fmaxf(sf[nt][2], sf[nt][3]));
        }
        mn0 = fmaxf(mn0, __shfl_xor_sync(0xffffffffu, mn0, 1));
        mn0 = fmaxf(mn0, __shfl_xor_sync(0xffffffffu, mn0, 2));
        mn1 = fmaxf(mn1, __shfl_xor_sync(0xffffffffu, mn1, 1));
        mn1 = fmaxf(mn1, __shfl_xor_sync(0xffffffffu, mn1, 2));

        const bool changed = __any_sync(0xffffffffu, (mn0 > m0) || (mn1 > m1));
        if (changed) {
            const float c0 = exp2f(m0 - mn0), c1 = exp2f(m1 - mn1);
#pragma unroll
            for (int nt = 0; nt < 8; nt++) {
                of[nt][0] *= c0; of[nt][1] *= c0;
                of[nt][2] *= c1; of[nt][3] *= c1;
            }
            lfrag[0] *= c0; lfrag[2] *= c1;
        }
        m0 = mn0; m1 = mn1;

        uint32_t ph[8][2];
#pragma unroll
        for (int nt = 0; nt < 8; nt++) {
            ph[nt][0] = h2exp2u(pkh2(sf[nt][0] - m0, sf[nt][1] - m0));
            ph[nt][1] = h2exp2u(pkh2(sf[nt][2] - m1, sf[nt][3] - m1));
        }

#pragma unroll
        for (int kq = 0; kq < 4; kq++) {
            const uint32_t a0 = ph[2 * kq][0];
            const uint32_t a1 = ph[2 * kq][1];
            const uint32_t a2 = ph[2 * kq + 1][0];
            const uint32_t a3 = ph[2 * kq + 1][1];
            mma16816(lfrag, a0, a1, a2, a3, bones, bones);
#pragma unroll
            for (int dg = 0; dg < 4; dg++) {
                uint32_t vb[4];
                ldsm4t(vb, smem_u32(&Vs[cur][kq * 16 + lrow][dg * 16 + lcol]));
                mma16816(of[2 * dg],     a0, a1, a2, a3, vb[0], vb[1]);
                mma16816(of[2 * dg + 1], a0, a1, a2, a3, vb[2], vb[3]);
            }
        }
    }

    const float l0 = __shfl_sync(0xffffffffu, lfrag[0], lane & 28);
    const float l1 = __shfl_sync(0xffffffffu, lfrag[2], lane & 28);
    const float i0 = 1.f / l0, i1 = 1.f / l1;
    __half* d0 = ctx + (size_t)(b * TSEQ + q0 + wq * 16 + g) * DM + h * DK;
    __half* d1 = d0 + (size_t)8 * DM;
#pragma unroll
    for (int nt = 0; nt < 8; nt++) {
        const int col = nt * 8 + 2 * t;
        *(__half2*)(d0 + col) = __floats2half2_rn(of[nt][0] * i0, of[nt][1] * i0);
        *(__half2*)(d1 + col) = __floats2half2_rn(of[nt][2] * i1, of[nt][3] * i1);
    }
}

// ---------------- launch --------------------------------------------------------
extern "C" void kernel_launch(void* const* d_in, const int* in_sizes, int n_in,
                              void* d_out, int out_size)
{
    const float* Q    = (const float*)d_in[0];
    const float* Kin  = (const float*)d_in[1];
    const float* Vin  = (const float*)d_in[2];
    const int*   mask = (const int*)  d_in[3];
    const float* W_q  = (const float*)d_in[4];
    const float* b_q  = (const float*)d_in[5];
    const float* W_k  = (const float*)d_in[6];
    const float* b_k  = (const float*)d_in[7];
    const float* W_v  = (const float*)d_in[8];
    const float* b_v  = (const float*)d_in[9];
    const float* W_o  = (const float*)d_in[10];
    const float* b_o  = (const float*)d_in[11];
    float* out = (float*)d_out;

    unsigned short *hq, *hkc, *hvc, *hw, *qp, *kp, *vp, *ctx;
    int *idx, *cnt;
    cudaGetSymbolAddress((void**)&hq,  g_hq);
    cudaGetSymbolAddress((void**)&hkc, g_hkc);
    cudaGetSymbolAddress((void**)&hvc, g_hvc);
    cudaGetSymbolAddress((void**)&hw,  g_hw);
    cudaGetSymbolAddress((void**)&qp,  g_qp);
    cudaGetSymbolAddress((void**)&kp,  g_kp);
    cudaGetSymbolAddress((void**)&vp,  g_vp);
    cudaGetSymbolAddress((void**)&ctx, g_ctx);
    cudaGetSymbolAddress((void**)&idx, g_idx);
    cudaGetSymbolAddress((void**)&cnt, g_cnt);

    static bool attr_set = false;
    if (!attr_set) {
        cudaFuncSetAttribute(gemm_qkv, cudaFuncAttributeMaxDynamicSharedMemorySize, GEMM_SMEM_BYTES);
        cudaFuncSetAttribute(gemm_out, cudaFuncAttributeMaxDynamicSharedMemorySize, GEMM_SMEM_BYTES);
        attr_set = true;
    }

    const int nW = DM * DM;       // 1048576

    compact_mask<<<BATCH, 256>>>(mask, idx, cnt);

    prep<<<10240, 256>>>(Q, W_q, W_k, W_v, W_o, Kin, Vin, idx, cnt,
                         hq, hw, hkc, hvc);

    gemm_qkv<<<dim3(DM / 128, BT / 128, 3), 256, GEMM_SMEM_BYTES>>>(
        (const __half*)hq, (const __half*)hkc, (const __half*)hvc,
        (const __half*)hw, b_q, b_k, b_v,
        (__half*)qp, (__half*)kp, (__half*)vp, cnt);

    attn_h<<<dim3(TSEQ / 128, BATCH * HEADS), 256>>>(
        (const __half*)qp, (const __half*)kp, (const __half*)vp, cnt, (__half*)ctx);

    gemm_out<<<dim3(DM / 128, BT / 128), 256, GEMM_SMEM_BYTES>>>(
        (const __half*)ctx, (const __half*)(hw + 3 * (size_t)nW), b_o, out);
}

// round 16
// speedup vs baseline: 1.0476x; 1.0258x over previous
#include <cuda_runtime.h>
#include <cuda_fp16.h>
#include <cstdint>

#define BATCH   4
#define TSEQ    2048
#define DM      1024
#define HEADS   16
#define DK      64
#define BT      (BATCH * TSEQ)   // 8192
#define LOG2E   1.4426950408889634f

// ---------------- scratch (device globals) ----------------------------------
__device__ unsigned short g_hq[BT * DM];     // fp16 Q input
__device__ unsigned short g_hkc[BT * DM];    // fp16 K input, mask-compacted rows
__device__ unsigned short g_hvc[BT * DM];    // fp16 V input, mask-compacted rows
__device__ unsigned short g_hw[4][DM * DM];  // fp16 weights
__device__ unsigned short g_qp[BT * DM];     // projected q (pre-scaled, log2 domain)
__device__ unsigned short g_kp[BT * DM];     // projected k (compacted)
__device__ unsigned short g_vp[BT * DM];     // projected v (compacted)
__device__ unsigned short g_ctx[BT * DM];    // attention output
__device__ int g_idx[BATCH * TSEQ];          // valid key indices per batch
__device__ int g_cnt[BATCH];                 // valid key counts

// ---------------- ptx helpers ------------------------------------------------
__device__ __forceinline__ uint32_t smem_u32(const void* p) {
    return (uint32_t)__cvta_generic_to_shared(p);
}
__device__ __forceinline__ void ldsm4(uint32_t r[4], uint32_t a) {
    asm volatile("ldmatrix.sync.aligned.m8n8.x4.shared.b16 {%0,%1,%2,%3}, [%4];"
                 : "=r"(r[0]), "=r"(r[1]), "=r"(r[2]), "=r"(r[3]) : "r"(a));
}
__device__ __forceinline__ void ldsm4t(uint32_t r[4], uint32_t a) {
    asm volatile("ldmatrix.sync.aligned.m8n8.x4.trans.shared.b16 {%0,%1,%2,%3}, [%4];"
                 : "=r"(r[0]), "=r"(r[1]), "=r"(r[2]), "=r"(r[3]) : "r"(a));
}
__device__ __forceinline__ void mma16816(float c[4],
    uint32_t a0, uint32_t a1, uint32_t a2, uint32_t a3, uint32_t b0, uint32_t b1) {
    asm volatile(
        "mma.sync.aligned.m16n8k16.row.col.f32.f16.f16.f32 "
        "{%0,%1,%2,%3}, {%4,%5,%6,%7}, {%8,%9}, {%0,%1,%2,%3};\n"
        : "+f"(c[0]), "+f"(c[1]), "+f"(c[2]), "+f"(c[3])
        : "r"(a0), "r"(a1), "r"(a2), "r"(a3), "r"(b0), "r"(b1));
}
__device__ __forceinline__ void cp16(uint32_t s, const void* g) {
    asm volatile("cp.async.cg.shared.global [%0], [%1], 16;" :: "r"(s), "l"(g));
}
__device__ __forceinline__ void cp_commit() {
    asm volatile("cp.async.commit_group;");
}
template<int N> __device__ __forceinline__ void cp_wait() {
    asm volatile("cp.async.wait_group %0;" :: "n"(N));
}
__device__ __forceinline__ uint32_t pkh2(float x, float y) {
    __half2 h = __floats2half2_rn(x, y);
    return *reinterpret_cast<uint32_t*>(&h);
}
__device__ __forceinline__ uint32_t h2exp2u(uint32_t a) {
    uint32_t d;
    asm("ex2.approx.f16x2 %0, %1;" : "=r"(d) : "r"(a));
    return d;
}

// ---------------- prepA: compact (blocks 0-3) + Q cvt + 4x W cvt --------------
// Compaction blocks are FIRST in the grid so they start in wave 1 and run
// concurrently with the 6144 conversion blocks (previously a separate
// 4-block kernel that idled 97% of the chip).
__global__ void __launch_bounds__(256) prepA(
    const float* __restrict__ Q,
    const float* __restrict__ w0, const float* __restrict__ w1,
    const float* __restrict__ w2, const float* __restrict__ w3,
    const int* __restrict__ mask,
    unsigned short* __restrict__ hq, unsigned short* __restrict__ hw,
    int* __restrict__ idx, int* __restrict__ cnt)
{
    const int bid = blockIdx.x, tid = threadIdx.x;

    if (bid < 4) {
        // ---- per-batch mask compaction (deterministic prefix scan) ----
        const int b = bid;
        const int lane = tid & 31, wid = tid >> 5;
        __shared__ int wtot[8];
        __shared__ int sbase;
        if (tid == 0) sbase = 0;
        __syncthreads();

        for (int c = 0; c < TSEQ; c += 256) {
            const int i = c + tid;
            const int v = mask[b * TSEQ + i] != 0;
            const unsigned bal = __ballot_sync(0xffffffffu, v);
            if (lane == 0) wtot[wid] = __popc(bal);
            __syncthreads();
            int off = sbase;
            for (int w = 0; w < wid; w++) off += wtot[w];
            off += __popc(bal & ((1u << lane) - 1));
            if (v) idx[b * TSEQ + off] = i;
            __syncthreads();
            if (tid == 0) {
                int t = 0;
                for (int w = 0; w < 8; w++) t += wtot[w];
                sbase += t;
            }
            __syncthreads();
        }
        if (tid == 0) cnt[b] = sbase;
    } else if (bid < 4100) {
        // ---- Q fp32 -> fp16 ----
        const int i = ((bid - 4) * 256 + tid) * 8;
        float4 v0 = *(const float4*)(Q + i);
        float4 v1 = *(const float4*)(Q + i + 4);
        uint4 u;
        u.x = pkh2(v0.x, v0.y); u.y = pkh2(v0.z, v0.w);
        u.z = pkh2(v1.x, v1.y); u.w = pkh2(v1.z, v1.w);
        *(uint4*)(hq + i) = u;
    } else {
        // ---- weights fp32 -> fp16 ----
        const int wb = bid - 4100;
        const int z = wb >> 9;
        const float* s = (z == 0) ? w0 : (z == 1) ? w1 : (z == 2) ? w2 : w3;
        const int i = ((wb & 511) * 256 + tid) * 8;
        float4 v0 = *(const float4*)(s + i);
        float4 v1 = *(const float4*)(s + i + 4);
        uint4 u;
        u.x = pkh2(v0.x, v0.y); u.y = pkh2(v0.z, v0.w);
        u.z = pkh2(v1.x, v1.y); u.w = pkh2(v1.z, v1.w);
        *(uint4*)(hw + (size_t)z * (DM * DM) + i) = u;
    }
}

// ---------------- gatherKV: K/V gather + fp32 -> fp16 --------------------------
__global__ void __launch_bounds__(256) gatherKV(
    const float* __restrict__ K, const float* __restrict__ V,
    const int* __restrict__ idx, const int* __restrict__ cnt,
    unsigned short* __restrict__ kc, unsigned short* __restrict__ vc)
{
    const int row = blockIdx.x * 2 + (threadIdx.x >> 7);
    const int b = row >> 11, j = row & 2047;
    const int Nb = cnt[b];
    const int pad = (Nb + 127) & ~127;
    if (j >= pad) return;
    const int e = (threadIdx.x & 127) * 8;
    const size_t dst = (size_t)row * DM + e;
    if (j < Nb) {
        const size_t src = ((size_t)(b * TSEQ) + idx[b * TSEQ + j]) * DM + e;
        float4 k0 = *(const float4*)(K + src);
        float4 k1 = *(const float4*)(K + src + 4);
        float4 v0 = *(const float4*)(V + src);
        float4 v1 = *(const float4*)(V + src + 4);
        uint4 ku, vu;
        ku.x = pkh2(k0.x, k0.y); ku.y = pkh2(k0.z, k0.w);
        ku.z = pkh2(k1.x, k1.y); ku.w = pkh2(k1.z, k1.w);
        vu.x = pkh2(v0.x, v0.y); vu.y = pkh2(v0.z, v0.w);
        vu.z = pkh2(v1.x, v1.y); vu.w = pkh2(v1.z, v1.w);
        *(uint4*)(kc + dst) = ku;
        *(uint4*)(vc + dst) = vu;
    } else {
        *(uint4*)(kc + dst) = make_uint4(0, 0, 0, 0);
        *(uint4*)(vc + dst) = make_uint4(0, 0, 0, 0);
    }
}

// ---------------- GEMM body (R13 proven): 128x128, warp 64x32, 1 barrier ------
template<bool OUT_HALF>
__device__ __forceinline__ void gemm_body(
    const __half* __restrict__ A, const __half* __restrict__ W,
    const float* __restrict__ bias, void* __restrict__ Cv, float scale,
    int bm, int bn)
{
    __shared__ __half As[2][128][40];
    __shared__ __half Ws[2][128][40];

    const int tid = threadIdx.x, lane = tid & 31, wid = tid >> 5;
    const int g = lane >> 2, t = lane & 3;
    const int wm = (wid >> 2) * 64, wn = (wid & 3) * 32;

    const int r0 = tid >> 2;
    const int r1 = 64 + r0;
    const int o0 = (tid & 3) * 8;

    const __half* Ag = A + (size_t)bm * DM;
    const __half* Wg = W + (size_t)bn * DM;

    float acc[4][4][4] = {};

    auto stage = [&](int buf, int k0) {
        cp16(smem_u32(&As[buf][r0][o0]), Ag + (size_t)r0 * DM + k0 + o0);
        cp16(smem_u32(&As[buf][r1][o0]), Ag + (size_t)r1 * DM + k0 + o0);
        cp16(smem_u32(&Ws[buf][r0][o0]), Wg + (size_t)r0 * DM + k0 + o0);
        cp16(smem_u32(&Ws[buf][r1][o0]), Wg + (size_t)r1 * DM + k0 + o0);
    };

    stage(0, 0); cp_commit();

    const int lrow = lane & 15, lcol = (lane >> 4) * 8;

    for (int kt = 0; kt < 32; kt++) {
        const int cur = kt & 1;
        cp_wait<0>();
        __syncthreads();
        if (kt < 31) { stage(cur ^ 1, (kt + 1) * 32); cp_commit(); }

#pragma unroll
        for (int kk = 0; kk < 2; kk++) {
            uint32_t a[4][4], bf[2][4];
#pragma unroll
            for (int mt = 0; mt < 4; mt++)
                ldsm4(a[mt], smem_u32(&As[cur][wm + mt * 16 + lrow][kk * 16 + lcol]));
#pragma unroll
            for (int ng = 0; ng < 2; ng++)
                ldsm4(bf[ng], smem_u32(&Ws[cur][wn + ng * 16 + lrow][kk * 16 + lcol]));
#pragma unroll
            for (int mt = 0; mt < 4; mt++)
#pragma unroll
                for (int nt = 0; nt < 4; nt++) {
                    const uint32_t b0 = (nt & 1) ? bf[nt >> 1][1] : bf[nt >> 1][0];
                    const uint32_t b1 = (nt & 1) ? bf[nt >> 1][3] : bf[nt >> 1][2];
                    mma16816(acc[mt][nt], a[mt][0], a[mt][1], a[mt][2], a[mt][3], b0, b1);
                }
        }
    }

#pragma unroll
    for (int nt = 0; nt < 4; nt++) {
        const int col = bn + wn + nt * 8 + 2 * t;
        const float bb0 = bias[col], bb1 = bias[col + 1];
#pragma unroll
        for (int mt = 0; mt < 4; mt++) {
            const int row = bm + wm + mt * 16 + g;
            const float x0 = (acc[mt][nt][0] + bb0) * scale;
            const float x1 = (acc[mt][nt][1] + bb1) * scale;
            const float x2 = (acc[mt][nt][2] + bb0) * scale;
            const float x3 = (acc[mt][nt][3] + bb1) * scale;
            if (OUT_HALF) {
                __half* C = (__half*)Cv;
                *(__half2*)(C + (size_t)row * DM + col)       = __floats2half2_rn(x0, x1);
                *(__half2*)(C + (size_t)(row + 8) * DM + col) = __floats2half2_rn(x2, x3);
            } else {
                float* C = (float*)Cv;
                *(float2*)(C + (size_t)row * DM + col)       = make_float2(x0, x1);
                *(float2*)(C + (size_t)(row + 8) * DM + col) = make_float2(x2, x3);
            }
        }
    }
}

__global__ void __launch_bounds__(256) gemm_qkv(
    const __half* __restrict__ Aq, const __half* __restrict__ Ak,
    const __half* __restrict__ Av, const __half* __restrict__ Wall,
    const float* __restrict__ bq, const float* __restrict__ bk,
    const float* __restrict__ bv,
    __half* __restrict__ Cq, __half* __restrict__ Ck, __half* __restrict__ Cv2,
    const int* __restrict__ cnt)
{
    const int z = blockIdx.z;
    const int bm = blockIdx.y * 128, bn = blockIdx.x * 128;
    if (z != 0) {
        const int Nb = cnt[bm >> 11];
        if ((bm & 2047) >= ((Nb + 127) & ~127)) return;
    }
    const __half* A = (z == 0) ? Aq : (z == 1) ? Ak : Av;
    const __half* W = Wall + (size_t)z * (DM * DM);
    const float* bias = (z == 0) ? bq : (z == 1) ? bk : bv;
    __half* C = (z == 0) ? Cq : (z == 1) ? Ck : Cv2;
    const float scale = (z == 0) ? (0.125f * LOG2E) : 1.0f;
    gemm_body<true>(A, W, bias, C, scale, bm, bn);
}

__global__ void __launch_bounds__(256) gemm_out(
    const __half* __restrict__ A, const __half* __restrict__ W,
    const float* __restrict__ bias, float* __restrict__ C)
{
    gemm_body<false>(A, W, bias, C, 1.0f, blockIdx.y * 128, blockIdx.x * 128);
}

// ---------------- fp16 flash attention (R13 proven config) --------------------
__global__ void __launch_bounds__(256) attn_h(
    const __half* __restrict__ qp, const __half* __restrict__ kp,
    const __half* __restrict__ vp, const int* __restrict__ cnt,
    __half* __restrict__ ctx)
{
    __shared__ __half Ks[2][64][72];
    __shared__ __half Vs[2][64][72];

    const int tid = threadIdx.x, lane = tid & 31, wq = tid >> 5;
    const int g = lane >> 2, t = lane & 3;
    const int bh = blockIdx.y, b = bh >> 4, h = bh & 15;
    const int q0 = blockIdx.x * 128;
    const int Nb = cnt[b];
    const int NT = (Nb + 63) >> 6;
    const bool partial = (Nb & 63) != 0;

    const uint32_t bones = (g == 0) ? 0x3C003C00u : 0u;

    const __half* kg = kp + (size_t)b * TSEQ * DM + h * DK;
    const __half* vg = vp + (size_t)b * TSEQ * DM + h * DK;

    uint32_t qf[4][4];
    {
        const __half* qb  = qp + (size_t)(b * TSEQ + q0 + wq * 16) * DM + h * DK;
        const __half* qr0 = qb + (size_t)g * DM + 2 * t;
        const __half* qr1 = qb + (size_t)(g + 8) * DM + 2 * t;
#pragma unroll
        for (int ks = 0; ks < 4; ks++) {
            qf[ks][0] = *(const uint32_t*)(qr0 + ks * 16);
            qf[ks][1] = *(const uint32_t*)(qr1 + ks * 16);
            qf[ks][2] = *(const uint32_t*)(qr0 + ks * 16 + 8);
            qf[ks][3] = *(const uint32_t*)(qr1 + ks * 16 + 8);
        }
    }

    const int sr0 = tid >> 3;
    const int sr1 = 32 + sr0;
    const int so  = (tid & 7) * 8;

    auto stage = [&](int buf, int j0) {
        cp16(smem_u32(&Ks[buf][sr0][so]), kg + (size_t)(j0 + sr0) * DM + so);
        cp16(smem_u32(&Ks[buf][sr1][so]), kg + (size_t)(j0 + sr1) * DM + so);
        cp16(smem_u32(&Vs[buf][sr0][so]), vg + (size_t)(j0 + sr0) * DM + so);
        cp16(smem_u32(&Vs[buf][sr1][so]), vg + (size_t)(j0 + sr1) * DM + so);
    };

    float of[8][4] = {};
    float lfrag[4] = {};
    float m0 = -1e30f, m1 = -1e30f;

    stage(0, 0); cp_commit();

    const int lrow = lane & 15, lcol = (lane >> 4) * 8;

    for (int jt = 0; jt < NT; jt++) {
        const int cur = jt & 1;
        cp_wait<0>();
        __syncthreads();
        if (jt < NT - 1) { stage(cur ^ 1, (jt + 1) * 64); cp_commit(); }

        float sf[8][4] = {};
#pragma unroll
        for (int ks = 0; ks < 4; ks++)
#pragma unroll
            for (int ng = 0; ng < 4; ng++) {
                uint32_t kb[4];
                ldsm4(kb, smem_u32(&Ks[cur][ng * 16 + lrow][ks * 16 + lcol]));
                mma16816(sf[2 * ng],     qf[ks][0], qf[ks][1], qf[ks][2], qf[ks][3], kb[0], kb[2]);
                mma16816(sf[2 * ng + 1], qf[ks][0], qf[ks][1], qf[ks][2], qf[ks][3], kb[1], kb[3]);
            }

        if (partial && jt == NT - 1) {
            const int jb = jt * 64 + 2 * t;
#pragma unroll
            for (int nt = 0; nt < 8; nt++) {
                const float a0 = (jb + nt * 8)     < Nb ? 0.f : -1e30f;
                const float a1 = (jb + nt * 8 + 1) < Nb ? 0.f : -1e30f;
                sf[nt][0] += a0; sf[nt][1] += a1;
                sf[nt][2] += a0; sf[nt][3] += a1;
            }
        }

        float mn0 = m0, mn1 = m1;
#pragma unroll
        for (int nt = 0; nt < 8; nt++) {
            mn0 = fmaxf(mn0, fmaxf(sf[nt][0], sf[nt][1]));
            mn1 = fmaxf(mn1, fmaxf(sf[nt][2], sf[nt][3]));
        }
        mn0 = fmaxf(mn0, __shfl_xor_sync(0xffffffffu, mn0, 1));
        mn0 = fmaxf(mn0, __shfl_xor_sync(0xffffffffu, mn0, 2));
        mn1 = fmaxf(mn1, __shfl_xor_sync(0xffffffffu, mn1, 1));
        mn1 = fmaxf(mn1, __shfl_xor_sync(0xffffffffu, mn1, 2));

        const bool changed = __any_sync(0xffffffffu, (mn0 > m0) || (mn1 > m1));
        if (changed) {
            const float c0 = exp2f(m0 - mn0), c1 = exp2f(m1 - mn1);
#pragma unroll
            for (int nt = 0; nt < 8; nt++) {
                of[nt][0] *= c0; of[nt][1] *= c0;
                of[nt][2] *= c1; of[nt][3] *= c1;
            }
            lfrag[0] *= c0; lfrag[2] *= c1;
        }
        m0 = mn0; m1 = mn1;

        uint32_t ph[8][2];
#pragma unroll
        for (int nt = 0; nt < 8; nt++) {
            ph[nt][0] = h2exp2u(pkh2(sf[nt][0] - m0, sf[nt][1] - m0));
            ph[nt][1] = h2exp2u(pkh2(sf[nt][2] - m1, sf[nt][3] - m1));
        }

#pragma unroll
        for (int kq = 0; kq < 4; kq++) {
            const uint32_t a0 = ph[2 * kq][0];
            const uint32_t a1 = ph[2 * kq][1];
            const uint32_t a2 = ph[2 * kq + 1][0];
            const uint32_t a3 = ph[2 * kq + 1][1];
            mma16816(lfrag, a0, a1, a2, a3, bones, bones);
#pragma unroll
            for (int dg = 0; dg < 4; dg++) {
                uint32_t vb[4];
                ldsm4t(vb, smem_u32(&Vs[cur][kq * 16 + lrow][dg * 16 + lcol]));
                mma16816(of[2 * dg],     a0, a1, a2, a3, vb[0], vb[1]);
                mma16816(of[2 * dg + 1], a0, a1, a2, a3, vb[2], vb[3]);
            }
        }
    }

    const float l0 = __shfl_sync(0xffffffffu, lfrag[0], lane & 28);
    const float l1 = __shfl_sync(0xffffffffu, lfrag[2], lane & 28);
    const float i0 = 1.f / l0, i1 = 1.f / l1;
    __half* d0 = ctx + (size_t)(b * TSEQ + q0 + wq * 16 + g) * DM + h * DK;
    __half* d1 = d0 + (size_t)8 * DM;
#pragma unroll
    for (int nt = 0; nt < 8; nt++) {
        const int col = nt * 8 + 2 * t;
        *(__half2*)(d0 + col) = __floats2half2_rn(of[nt][0] * i0, of[nt][1] * i0);
        *(__half2*)(d1 + col) = __floats2half2_rn(of[nt][2] * i1, of[nt][3] * i1);
    }
}

// ---------------- launch --------------------------------------------------------
extern "C" void kernel_launch(void* const* d_in, const int* in_sizes, int n_in,
                              void* d_out, int out_size)
{
    const float* Q    = (const float*)d_in[0];
    const float* Kin  = (const float*)d_in[1];
    const float* Vin  = (const float*)d_in[2];
    const int*   mask = (const int*)  d_in[3];
    const float* W_q  = (const float*)d_in[4];
    const float* b_q  = (const float*)d_in[5];
    const float* W_k  = (const float*)d_in[6];
    const float* b_k  = (const float*)d_in[7];
    const float* W_v  = (const float*)d_in[8];
    const float* b_v  = (const float*)d_in[9];
    const float* W_o  = (const float*)d_in[10];
    const float* b_o  = (const float*)d_in[11];
    float* out = (float*)d_out;

    unsigned short *hq, *hkc, *hvc, *hw, *qp, *kp, *vp, *ctx;
    int *idx, *cnt;
    cudaGetSymbolAddress((void**)&hq,  g_hq);
    cudaGetSymbolAddress((void**)&hkc, g_hkc);
    cudaGetSymbolAddress((void**)&hvc, g_hvc);
    cudaGetSymbolAddress((void**)&hw,  g_hw);
    cudaGetSymbolAddress((void**)&qp,  g_qp);
    cudaGetSymbolAddress((void**)&kp,  g_kp);
    cudaGetSymbolAddress((void**)&vp,  g_vp);
    cudaGetSymbolAddress((void**)&ctx, g_ctx);
    cudaGetSymbolAddress((void**)&idx, g_idx);
    cudaGetSymbolAddress((void**)&cnt, g_cnt);

    const int nW = DM * DM;       // 1048576

    prepA<<<6148, 256>>>(Q, W_q, W_k, W_v, W_o, mask, hq, hw, idx, cnt);

    gatherKV<<<BT / 2, 256>>>(Kin, Vin, idx, cnt, hkc, hvc);

    gemm_qkv<<<dim3(DM / 128, BT / 128, 3), 256>>>(
        (const __half*)hq, (const __half*)hkc, (const __half*)hvc,
        (const __half*)hw, b_q, b_k, b_v,
        (__half*)qp, (__half*)kp, (__half*)vp, cnt);

    attn_h<<<dim3(TSEQ / 128, BATCH * HEADS), 256>>>(
        (const __half*)qp, (const __half*)kp, (const __half*)vp, cnt, (__half*)ctx);

    gemm_out<<<dim3(DM / 128, BT / 128), 256>>>(
        (const __half*)ctx, (const __half*)(hw + 3 * (size_t)nW), b_o, out);
}